// round 12
// baseline (speedup 1.0000x reference)
#include <cuda_runtime.h>
#include <cuda_bf16.h>
#include <cstdint>

// CRF log-likelihood: B=256, M=1024, D=128, N=26.  SINGLE cooperative kernel:
//   blocks 0..511    : scanner (seq, half).  warp0 = forward/adjoint scan,
//                      warp1 = label score.  Consume e tiles as flagged.
//   blocks 512..1023 : producer (seq, half).  HMMA bf16 e-tiles, written to
//                      g_e in the consumer's order; release flag per tile.
//   Last scanner block (atomic ticket) does the final combine -> out[0].

#define B_ 256
#define M_ 1024
#define D_ 128
#define N_ 26
#define EST 32
#define FULLM 0xffffffffu
#define XS 136
typedef unsigned long long ull;

__device__ float g_e[(size_t)B_ * M_ * EST];
__device__ int   g_flag[512 * 4];            // per (scanblock, tile)
__device__ float g_midv[B_ * 32];
__device__ float g_midu[B_ * 32];
__device__ float g_cfw[B_];
__device__ float g_cbw[B_];
__device__ float g_scpart[512];
__device__ int   g_done;

__device__ __forceinline__ uint32_t bf2(float x, float y) {
    uint32_t p;
    asm("cvt.rn.bf16x2.f32 %0, %1, %2;" : "=r"(p) : "f"(y), "f"(x));
    return p;
}
__device__ __forceinline__ ull fma2(ull a, ull b, ull c) {
    ull d;
    asm("fma.rn.f32x2 %0, %1, %2, %3;" : "=l"(d) : "l"(a), "l"(b), "l"(c));
    return d;
}
__device__ __forceinline__ ull packf2(float lo, float hi) {
    return (ull)__float_as_uint(lo) | ((ull)__float_as_uint(hi) << 32);
}
__device__ __forceinline__ void mma_bf16(float* d, const uint32_t* a,
                                         const uint32_t* b) {
    asm volatile(
        "mma.sync.aligned.m16n8k16.row.col.f32.bf16.bf16.f32 "
        "{%0,%1,%2,%3}, {%4,%5,%6,%7}, {%8,%9}, {%0,%1,%2,%3};"
        : "+f"(d[0]), "+f"(d[1]), "+f"(d[2]), "+f"(d[3])
        : "r"(a[0]), "r"(a[1]), "r"(a[2]), "r"(a[3]), "r"(b[0]), "r"(b[1]));
}

__device__ __forceinline__ float dot26p(const ulonglong2 t2[7], const ull* E2) {
    ull a0 = 0ull, a1 = 0ull;
    a0 = fma2(t2[0].x, E2[0], a0);  a1 = fma2(t2[0].y, E2[1], a1);
    a0 = fma2(t2[1].x, E2[2], a0);  a1 = fma2(t2[1].y, E2[3], a1);
    a0 = fma2(t2[2].x, E2[4], a0);  a1 = fma2(t2[2].y, E2[5], a1);
    a0 = fma2(t2[3].x, E2[6], a0);  a1 = fma2(t2[3].y, E2[7], a1);
    a0 = fma2(t2[4].x, E2[8], a0);  a1 = fma2(t2[4].y, E2[9], a1);
    a0 = fma2(t2[5].x, E2[10], a0); a1 = fma2(t2[5].y, E2[11], a1);
    a0 = fma2(t2[6].x, E2[12], a0);
    float l0 = __int_as_float((int)(a0 & 0xffffffffull));
    float h0 = __int_as_float((int)(a0 >> 32));
    float l1 = __int_as_float((int)(a1 & 0xffffffffull));
    float h1 = __int_as_float((int)(a1 >> 32));
    return (l0 + h0) + (l1 + h1);
}

__device__ __forceinline__ void wait_flag(int idx) {
    while (((volatile int*)g_flag)[idx] == 0) __nanosleep(64);
    __threadfence();
}

// producer: one 32-row warp-slice of a 128-row e tile, straight to g_e
__device__ __forceinline__ void produce_slice(const float* __restrict__ X,
                                              const __nv_bfloat16* Wb,
                                              size_t rowbase, int warp, int lane) {
    const int q = lane & 3, r8 = lane >> 2;
    const size_t wrow = rowbase + warp * 32;

    float acc[2][4][4];
#pragma unroll
    for (int mt = 0; mt < 2; mt++)
#pragma unroll
        for (int nt = 0; nt < 4; nt++)
#pragma unroll
            for (int e = 0; e < 4; e++) acc[mt][nt][e] = 0.f;

#pragma unroll
    for (int ks = 0; ks < 8; ks++) {
        const int k0 = ks * 16;
        uint32_t afrag[2][4], bfrag[4][2];
#pragma unroll
        for (int mt = 0; mt < 2; mt++) {
            const float* xr  = X + (wrow + mt * 16 + r8) * D_;
            const float* xr8 = xr + 8 * D_;
            float2 v0 = __ldg((const float2*)(xr  + k0 + 2 * q));
            float2 v1 = __ldg((const float2*)(xr8 + k0 + 2 * q));
            float2 v2 = __ldg((const float2*)(xr  + k0 + 8 + 2 * q));
            float2 v3 = __ldg((const float2*)(xr8 + k0 + 8 + 2 * q));
            afrag[mt][0] = bf2(v0.x, v0.y);
            afrag[mt][1] = bf2(v1.x, v1.y);
            afrag[mt][2] = bf2(v2.x, v2.y);
            afrag[mt][3] = bf2(v3.x, v3.y);
        }
#pragma unroll
        for (int nt = 0; nt < 4; nt++) {
            const int n = nt * 8 + r8;
            bfrag[nt][0] = *(const uint32_t*)&Wb[n * XS + k0 + 2 * q];
            bfrag[nt][1] = *(const uint32_t*)&Wb[n * XS + k0 + 8 + 2 * q];
        }
#pragma unroll
        for (int mt = 0; mt < 2; mt++)
#pragma unroll
            for (int nt = 0; nt < 4; nt++)
                mma_bf16(acc[mt][nt], afrag[mt], bfrag[nt]);
    }
#pragma unroll
    for (int mt = 0; mt < 2; mt++)
#pragma unroll
        for (int nt = 0; nt < 4; nt++) {
            const size_t r0 = wrow + mt * 16 + r8;
            const int c = nt * 8 + 2 * q;
            *(float2*)(g_e + r0 * EST + c) =
                make_float2(acc[mt][nt][0], acc[mt][nt][1]);
            *(float2*)(g_e + (r0 + 8) * EST + c) =
                make_float2(acc[mt][nt][2], acc[mt][nt][3]);
        }
}

// ---------------------------------------------------------------------------
__global__ __launch_bounds__(128) void crf_mega(const float* __restrict__ X,
                                                const int* __restrict__ labels,
                                                const float* __restrict__ W,
                                                const float* __restrict__ Tg,
                                                float* __restrict__ out) {
    __shared__ __nv_bfloat16 Wb[32 * XS];
    __shared__ __align__(16) float vxch[2][32];
    __shared__ int s_ticket;
    __shared__ float s_red[4];

    const int b    = blockIdx.x;
    const int tid  = threadIdx.x;
    const int warp = tid >> 5;
    const int lane = tid & 31;

    if (b >= 512) {
        // ==================== PRODUCER ====================
        const int eb = b - 512;
        const int seq = eb >> 1, half = eb & 1;
        const size_t base = (size_t)seq * M_ + half * 512;

        for (int i = tid; i < 1024; i += 128) {
            const int row = i >> 5, c4 = i & 31;
            float4 v = make_float4(0.f, 0.f, 0.f, 0.f);
            if (row < N_) v = __ldg((const float4*)(W + row * D_) + c4);
            uint2 p = make_uint2(bf2(v.x, v.y), bf2(v.z, v.w));
            *(uint2*)&Wb[row * XS + c4 * 4] = p;
        }
        __syncthreads();

        for (int c = 0; c < 4; c++) {
            const int tg = half ? (3 - c) : c;
            produce_slice(X, Wb, base + (size_t)tg * 128, warp, lane);
            __threadfence();
            __syncthreads();
            if (tid == 0) atomicExch(&g_flag[eb * 4 + tg], 1);
        }
        return;
    }

    // ==================== SCANNER ====================
    const int sb = b;
    const int seq = sb >> 1, bwd = sb & 1;
    const int halfOff = bwd ? 512 : 0;
    const float* er = g_e + (size_t)seq * M_ * EST;
    const int* lab  = labels + seq * M_;
    const bool act  = lane < N_;

    if (warp == 0) {
        // ---- scan warp ----
        ull ET2[13];
        const int la = act ? lane : 25;
#pragma unroll
        for (int i = 0; i < 13; i++) {
            float lo, hi;
            if (!bwd) { lo = __expf(__ldg(Tg + (2 * i) * 26 + la));
                        hi = __expf(__ldg(Tg + (2 * i + 1) * 26 + la)); }
            else      { lo = __expf(__ldg(Tg + la * 26 + 2 * i));
                        hi = __expf(__ldg(Tg + la * 26 + 2 * i + 1)); }
            ET2[i] = act ? packf2(lo, hi) : 0ull;
        }

        float ebuf[8], Cl2 = 0.f, vstate;
        int par = 0, rc = 0;

        if (!bwd) {
            wait_flag(sb * 4 + 0);
            vstate = act ? __expf(__ldg(er + lane)) : 0.f;      // v_0
            vxch[0][lane] = act ? vstate : 0.f;
            __syncwarp();

            for (int c = 0; c < 4; c++) {
                if (c > 0) wait_flag(sb * 4 + c);
                const int mstart = (c == 0) ? 1 : c * 128;
                const int mend   = c * 128 + 127;
#pragma unroll
                for (int i = 0; i < 8; i++)
                    ebuf[i] = act ? __ldg(er + (size_t)(mstart + i) * EST + lane) : 0.f;
                float Ecur = __expf(ebuf[0]);
                for (int m = mstart; m <= mend; m++) {
                    const int j = (m - mstart) & 7;
                    float Enext = __expf(ebuf[(j + 1) & 7]);
                    ulonglong2 t2[7];
                    const ulonglong2* vp = (const ulonglong2*)&vxch[par][0];
#pragma unroll
                    for (int qq = 0; qq < 7; qq++) t2[qq] = vp[qq];
                    vstate = Ecur * dot26p(t2, ET2);
                    if (((++rc) & 7) == 0) {
                        float pf = __int_as_float((int)(t2[0].x & 0xffffffffull));
                        int ex = (__float_as_int(pf) >> 23) - 127;
                        Cl2 += (float)ex;
                        vstate = __int_as_float(__float_as_int(vstate) - (ex << 23));
                    }
                    if (m + 8 <= mend)
                        ebuf[j] = act ? __ldg(er + (size_t)(m + 8) * EST + lane) : 0.f;
                    vxch[par ^ 1][lane] = act ? vstate : 0.f;
                    __syncwarp();
                    par ^= 1;
                    Ecur = Enext;
                }
            }
            if (act) g_midv[seq * 32 + lane] = vstate;
            if (lane == 0) g_cfw[seq] = Cl2;
        } else {
            // adjoint: rows 1023 down to 512 of this sequence
            for (int c = 0; c < 4; c++) {
                wait_flag(sb * 4 + (3 - c));
                if (c == 0) {
                    float E0 = act ? __expf(__ldg(er + (size_t)1023 * EST + lane)) : 0.f;
                    vxch[0][lane] = act ? E0 : 0.f;      // s_1023
                    __syncwarp();
                }
                const int rstart = (c == 0) ? 1022 : (1023 - 128 * c);
                const int rend   = 1024 - 128 * (c + 1);
#pragma unroll
                for (int i = 0; i < 8; i++)
                    ebuf[i] = act ? __ldg(er + (size_t)(rstart - i) * EST + lane) : 0.f;
                float Ecur = __expf(ebuf[0]);
                for (int r = rstart; r >= rend; r--) {
                    const int j = (rstart - r) & 7;
                    float Enext = __expf(ebuf[(j + 1) & 7]);
                    ulonglong2 t2[7];
                    const ulonglong2* vp = (const ulonglong2*)&vxch[par][0];
#pragma unroll
                    for (int qq = 0; qq < 7; qq++) t2[qq] = vp[qq];
                    float u = dot26p(t2, ET2);
                    if (((++rc) & 7) == 0) {
                        float pf = __int_as_float((int)(t2[0].x & 0xffffffffull));
                        int ex = (__float_as_int(pf) >> 23) - 127;
                        Cl2 += (float)ex;
                        u = __int_as_float(__float_as_int(u) - (ex << 23));
                    }
                    if (r - 8 >= rend)
                        ebuf[j] = act ? __ldg(er + (size_t)(r - 8) * EST + lane) : 0.f;
                    vstate = u;
                    vxch[par ^ 1][lane] = act ? (Ecur * u) : 0.f;   // s_{r}
                    __syncwarp();
                    par ^= 1;
                    Ecur = Enext;
                }
            }
            {   // u_511 from s_512
                ulonglong2 t2[7];
                const ulonglong2* vp = (const ulonglong2*)&vxch[par][0];
#pragma unroll
                for (int qq = 0; qq < 7; qq++) t2[qq] = vp[qq];
                vstate = dot26p(t2, ET2);
            }
            if (act) g_midu[seq * 32 + lane] = vstate;
            if (lane == 0) g_cbw[seq] = Cl2;
        }
    } else if (warp == 1) {
        // ---- score warp ----
        float se = 0.f, st = 0.f;
        for (int c = 0; c < 4; c++) {
            const int tg = bwd ? (3 - c) : c;
            wait_flag(sb * 4 + tg);
            const int m0 = halfOff + tg * 128 + lane * 4;
            int4 q4 = __ldg((const int4*)(lab + m0));
            se += __ldg(er + (size_t)(m0 + 0) * EST + q4.x);
            se += __ldg(er + (size_t)(m0 + 1) * EST + q4.y);
            se += __ldg(er + (size_t)(m0 + 2) * EST + q4.z);
            se += __ldg(er + (size_t)(m0 + 3) * EST + q4.w);
            st += __ldg(Tg + q4.x * 26 + q4.y);
            st += __ldg(Tg + q4.y * 26 + q4.z);
            st += __ldg(Tg + q4.z * 26 + q4.w);
            const int loc3 = tg * 128 + lane * 4 + 3;
            if (loc3 < 511) {
                int yn = __ldg(lab + m0 + 4);
                st += __ldg(Tg + q4.w * 26 + yn);
            }
        }
        float sc = se + st;
#pragma unroll
        for (int off = 16; off; off >>= 1)
            sc += __shfl_xor_sync(FULLM, sc, off);
        if (lane == 0) g_scpart[sb] = sc;
    }
    // warps 2,3 fall through

    __threadfence();
    __syncthreads();
    if (tid < 4) g_flag[sb * 4 + tid] = 0;     // reset for next replay
    if (tid == 0) s_ticket = atomicAdd(&g_done, 1);
    __syncthreads();

    if (s_ticket == 511) {
        // ---- last scanner block: combine ----
        __threadfence();
        float acc = 0.f;
        for (int s = tid; s < 256; s += 128) {
            float pv = 0.f;
#pragma unroll
            for (int a = 0; a < N_; a++)
                pv += g_midv[s * 32 + a] * g_midu[s * 32 + a];
            const int y0 = __ldg(labels + s * M_ + 511);
            const int y1 = __ldg(labels + s * M_ + 512);
            float sc = g_scpart[2 * s] + g_scpart[2 * s + 1]
                     + __ldg(Tg + y0 * 26 + y1);
            acc += sc - (g_cfw[s] + g_cbw[s]) * 0.6931471805599453f - logf(pv);
        }
#pragma unroll
        for (int off = 16; off; off >>= 1)
            acc += __shfl_xor_sync(FULLM, acc, off);
        if (lane == 0) s_red[warp] = acc;
        __syncthreads();
        if (tid == 0) {
            out[0] = (s_red[0] + s_red[1] + s_red[2] + s_red[3]) * (1.0f / 256.0f);
            g_done = 0;                         // reset for next replay
        }
    }
}

// ---------------------------------------------------------------------------
extern "C" void kernel_launch(void* const* d_in, const int* in_sizes, int n_in,
                              void* d_out, int out_size) {
    const float* X      = (const float*)d_in[0];   // [256,1024,128] f32
    const int*   labels = (const int*)d_in[1];     // [256,1024] i32
    const float* W      = (const float*)d_in[2];   // [26,128] f32
    const float* Tm     = (const float*)d_in[3];   // [26,26] f32

    crf_mega<<<1024, 128>>>(X, labels, W, Tm, (float*)d_out);
}

// round 15
// speedup vs baseline: 2.1740x; 2.1740x over previous
#include <cuda_runtime.h>
#include <cuda_bf16.h>
#include <cstdint>

// CRF log-likelihood: B=256, M=1024, D=128, N=26.   R7 skeleton:
//   1) emis_hmma   : e = X @ W^T, HMMA bf16, A-fragments DIRECT from X
//                    (no smem staging), grid 2048, C -> g_e (stride 32)
//   2) scan_kernel : split fwd/adjoint scan, smem-broadcast + f32x2 dot
//   3) score_combine, 4) reduce_kernel : unchanged
//
// tcgen05 unavailable (harness targets sm_103 without 'a').

#define B_ 256
#define M_ 1024
#define D_ 128
#define N_ 26
#define EST 32
#define FULLM 0xffffffffu
#define XS 136
typedef unsigned long long ull;

__device__ float g_e[(size_t)B_ * M_ * EST];
__device__ float g_midv[B_ * 32];
__device__ float g_midu[B_ * 32];
__device__ float g_cfw[B_];
__device__ float g_cbw[B_];
__device__ float g_res[B_];

__device__ __forceinline__ uint32_t bf2(float x, float y) {
    uint32_t p;
    asm("cvt.rn.bf16x2.f32 %0, %1, %2;" : "=r"(p) : "f"(y), "f"(x));
    return p;
}
__device__ __forceinline__ ull fma2(ull a, ull b, ull c) {
    ull d;
    asm("fma.rn.f32x2 %0, %1, %2, %3;" : "=l"(d) : "l"(a), "l"(b), "l"(c));
    return d;
}
__device__ __forceinline__ ull packf2(float lo, float hi) {
    return (ull)__float_as_uint(lo) | ((ull)__float_as_uint(hi) << 32);
}
__device__ __forceinline__ void mma_bf16(float* d, const uint32_t* a,
                                         const uint32_t* b) {
    asm volatile(
        "mma.sync.aligned.m16n8k16.row.col.f32.bf16.bf16.f32 "
        "{%0,%1,%2,%3}, {%4,%5,%6,%7}, {%8,%9}, {%0,%1,%2,%3};"
        : "+f"(d[0]), "+f"(d[1]), "+f"(d[2]), "+f"(d[3])
        : "r"(a[0]), "r"(a[1]), "r"(a[2]), "r"(a[3]), "r"(b[0]), "r"(b[1]));
}

// 26-dot: 7x 16B broadcast state vs packed per-lane coefficients (13 FFMA2)
__device__ __forceinline__ float dot26p(const ulonglong2 t2[7], const ull* E2) {
    ull a0 = 0ull, a1 = 0ull;
    a0 = fma2(t2[0].x, E2[0], a0);  a1 = fma2(t2[0].y, E2[1], a1);
    a0 = fma2(t2[1].x, E2[2], a0);  a1 = fma2(t2[1].y, E2[3], a1);
    a0 = fma2(t2[2].x, E2[4], a0);  a1 = fma2(t2[2].y, E2[5], a1);
    a0 = fma2(t2[3].x, E2[6], a0);  a1 = fma2(t2[3].y, E2[7], a1);
    a0 = fma2(t2[4].x, E2[8], a0);  a1 = fma2(t2[4].y, E2[9], a1);
    a0 = fma2(t2[5].x, E2[10], a0); a1 = fma2(t2[5].y, E2[11], a1);
    a0 = fma2(t2[6].x, E2[12], a0);            // labels 24,25
    float l0 = __int_as_float((int)(a0 & 0xffffffffull));
    float h0 = __int_as_float((int)(a0 >> 32));
    float l1 = __int_as_float((int)(a1 & 0xffffffffull));
    float h1 = __int_as_float((int)(a1 >> 32));
    return (l0 + h0) + (l1 + h1);
}

// ---------------------------------------------------------------------------
// Kernel 1: e = X @ W^T, direct-load HMMA.  grid 2048 x 128 thr.
//   Block = 128 rows; warp = 32-row slice.  A frags via LDG.64 from X
//   (4 lanes q=0..3 cover a 32B sector), B from Wb smem, C -> g_e.
// ---------------------------------------------------------------------------
__global__ __launch_bounds__(128) void emis_hmma(const float* __restrict__ X,
                                                 const float* __restrict__ W) {
    __shared__ __nv_bfloat16 Wb[32 * XS];

    const int tid  = threadIdx.x;
    const int warp = tid >> 5;
    const int lane = tid & 31;
    const int q    = lane & 3;
    const int r8   = lane >> 2;

    for (int i = tid; i < 1024; i += 128) {
        const int row = i >> 5, c4 = i & 31;
        float4 v = make_float4(0.f, 0.f, 0.f, 0.f);
        if (row < N_) v = __ldg((const float4*)(W + row * D_) + c4);
        uint2 p = make_uint2(bf2(v.x, v.y), bf2(v.z, v.w));
        *(uint2*)&Wb[row * XS + c4 * 4] = p;
    }
    __syncthreads();

    const size_t wrow = (size_t)blockIdx.x * 128 + warp * 32;

    float acc[2][4][4];
#pragma unroll
    for (int mt = 0; mt < 2; mt++)
#pragma unroll
        for (int nt = 0; nt < 4; nt++)
#pragma unroll
            for (int e = 0; e < 4; e++) acc[mt][nt][e] = 0.f;

#pragma unroll
    for (int ks = 0; ks < 8; ks++) {
        const int k0 = ks * 16;
        uint32_t afrag[2][4], bfrag[4][2];
#pragma unroll
        for (int mt = 0; mt < 2; mt++) {
            const float* xr  = X + (wrow + mt * 16 + r8) * D_;
            const float* xr8 = xr + 8 * D_;
            float2 v0 = __ldg((const float2*)(xr  + k0 + 2 * q));
            float2 v1 = __ldg((const float2*)(xr8 + k0 + 2 * q));
            float2 v2 = __ldg((const float2*)(xr  + k0 + 8 + 2 * q));
            float2 v3 = __ldg((const float2*)(xr8 + k0 + 8 + 2 * q));
            afrag[mt][0] = bf2(v0.x, v0.y);
            afrag[mt][1] = bf2(v1.x, v1.y);
            afrag[mt][2] = bf2(v2.x, v2.y);
            afrag[mt][3] = bf2(v3.x, v3.y);
        }
#pragma unroll
        for (int nt = 0; nt < 4; nt++) {
            const int n = nt * 8 + r8;
            bfrag[nt][0] = *(const uint32_t*)&Wb[n * XS + k0 + 2 * q];
            bfrag[nt][1] = *(const uint32_t*)&Wb[n * XS + k0 + 8 + 2 * q];
        }
#pragma unroll
        for (int mt = 0; mt < 2; mt++)
#pragma unroll
            for (int nt = 0; nt < 4; nt++)
                mma_bf16(acc[mt][nt], afrag[mt], bfrag[nt]);
    }

#pragma unroll
    for (int mt = 0; mt < 2; mt++)
#pragma unroll
        for (int nt = 0; nt < 4; nt++) {
            const size_t r0 = wrow + mt * 16 + r8;
            const int c = nt * 8 + 2 * q;
            *(float2*)(g_e + r0 * EST + c) =
                make_float2(acc[mt][nt][0], acc[mt][nt][1]);
            *(float2*)(g_e + (r0 + 8) * EST + c) =
                make_float2(acc[mt][nt][2], acc[mt][nt][3]);
        }
}

// ---------------------------------------------------------------------------
// Kernel 2: SPLIT scan.  even block -> forward, odd -> adjoint.
// ---------------------------------------------------------------------------
__global__ __launch_bounds__(32) void scan_kernel(const float* __restrict__ Tg) {
    __shared__ __align__(16) float vbuf[2][32];

    const int seq  = blockIdx.x >> 1;
    const int bwd  = blockIdx.x & 1;
    const int lane = threadIdx.x;
    const bool act = lane < N_;
    const float* er = g_e + (size_t)seq * M_ * EST;

    float Cl2 = 0.f;
    const int la = act ? lane : 25;

    ull ET2[13];
#pragma unroll
    for (int i = 0; i < 13; i++) {
        float lo, hi;
        if (!bwd) { lo = __expf(__ldg(Tg + (2 * i) * 26 + la));
                    hi = __expf(__ldg(Tg + (2 * i + 1) * 26 + la)); }
        else      { lo = __expf(__ldg(Tg + la * 26 + 2 * i));
                    hi = __expf(__ldg(Tg + la * 26 + 2 * i + 1)); }
        ET2[i] = act ? packf2(lo, hi) : 0ull;
    }

    if (!bwd) {
        // ---------------- forward ----------------
        float v = act ? __expf(__ldg(er + lane)) : 0.f;

        float ebuf[8];
#pragma unroll
        for (int i = 0; i < 8; i++)
            ebuf[i] = act ? __ldg(er + (size_t)(1 + i) * EST + lane) : 0.f;
        float Ecur = __expf(ebuf[0]);

        vbuf[0][lane] = act ? v : 0.f;
        __syncwarp();

        int m = 1;
        for (int blk = 0; blk < 63; blk++) {
#pragma unroll
            for (int j = 0; j < 8; j++) {
                float Enext = __expf(ebuf[(j + 1) & 7]);
                ulonglong2 t2[7];
                const ulonglong2* vp = (const ulonglong2*)&vbuf[j & 1][0];
#pragma unroll
                for (int qq = 0; qq < 7; qq++) t2[qq] = vp[qq];
                v = Ecur * dot26p(t2, ET2);
                Ecur = Enext;
                if (j == 7) {
                    float pf = __int_as_float((int)(t2[0].x & 0xffffffffull));
                    int ex = (__float_as_int(pf) >> 23) - 127;
                    Cl2 += (float)ex;
                    v = __int_as_float(__float_as_int(v) - (ex << 23));
                }
                const int mn = m + 8;
                if (mn <= 511)
                    ebuf[j] = act ? __ldg(er + (size_t)mn * EST + lane) : 0.f;
                vbuf[(j + 1) & 1][lane] = act ? v : 0.f;
                __syncwarp();
                m++;
            }
        }
#pragma unroll
        for (int j = 0; j < 7; j++) {
            float Enext = (j < 6) ? __expf(ebuf[j + 1]) : 1.f;
            ulonglong2 t2[7];
            const ulonglong2* vp = (const ulonglong2*)&vbuf[j & 1][0];
#pragma unroll
            for (int qq = 0; qq < 7; qq++) t2[qq] = vp[qq];
            v = Ecur * dot26p(t2, ET2);
            Ecur = Enext;
            vbuf[(j + 1) & 1][lane] = act ? v : 0.f;
            __syncwarp();
        }
        if (act) g_midv[seq * 32 + lane] = v;
        if (lane == 0) g_cfw[seq] = Cl2;
    } else {
        // ---------------- adjoint ----------------
        float u = act ? 1.f : 0.f;

        float ebuf[8];
#pragma unroll
        for (int i = 0; i < 8; i++)
            ebuf[i] = act ? __ldg(er + (size_t)(1023 - i) * EST + lane) : 0.f;
        float Ecur = __expf(ebuf[0]);

        vbuf[0][lane] = act ? (Ecur * u) : 0.f;
        __syncwarp();

        int k = 0;
        for (int blk = 0; blk < 64; blk++) {
#pragma unroll
            for (int j = 0; j < 8; j++) {
                float Enext = __expf(ebuf[(j + 1) & 7]);
                ulonglong2 t2[7];
                const ulonglong2* vp = (const ulonglong2*)&vbuf[j & 1][0];
#pragma unroll
                for (int qq = 0; qq < 7; qq++) t2[qq] = vp[qq];
                u = dot26p(t2, ET2);
                Ecur = Enext;
                if (j == 7) {
                    float pf = __int_as_float((int)(t2[0].x & 0xffffffffull));
                    int ex = (__float_as_int(pf) >> 23) - 127;
                    Cl2 += (float)ex;
                    u = __int_as_float(__float_as_int(u) - (ex << 23));
                }
                const int kn = k + 8;
                if (kn <= 511)
                    ebuf[j] = act ? __ldg(er + (size_t)(1023 - kn) * EST + lane) : 0.f;
                vbuf[(j + 1) & 1][lane] = act ? (Ecur * u) : 0.f;
                __syncwarp();
                k++;
            }
        }
        if (act) g_midu[seq * 32 + lane] = u;
        if (lane == 0) g_cbw[seq] = Cl2;
    }
}

// ---------------------------------------------------------------------------
// Kernel 3: unnormalized score + combine halves
// ---------------------------------------------------------------------------
__global__ __launch_bounds__(32) void score_combine(const int* __restrict__ labels,
                                                    const float* __restrict__ Tg) {
    const int seq  = blockIdx.x;
    const int lane = threadIdx.x;
    const float* er = g_e + (size_t)seq * M_ * EST;
    const int*  lab = labels + seq * M_;

    float pv = (lane < N_) ? g_midv[seq * 32 + lane] * g_midu[seq * 32 + lane] : 0.f;
#pragma unroll
    for (int off = 16; off; off >>= 1) pv += __shfl_xor_sync(FULLM, pv, off);

    int y[32];
    {
        const int4* lp = (const int4*)(lab + lane * 32);
#pragma unroll
        for (int i = 0; i < 8; i++) {
            int4 qd = __ldg(lp + i);
            y[i * 4] = qd.x; y[i * 4 + 1] = qd.y; y[i * 4 + 2] = qd.z; y[i * 4 + 3] = qd.w;
        }
    }
    int y_next0 = __shfl_down_sync(FULLM, y[0], 1);

    float se = 0.f, st = 0.f;
#pragma unroll
    for (int i = 0; i < 32; i++) {
        const int m = lane * 32 + i;
        se += __ldg(er + (size_t)m * EST + y[i]);
        const int yn = (i < 31) ? y[i + 1] : y_next0;
        if (m < 1023) st += __ldg(Tg + y[i] * 26 + yn);
    }
    float sc = se + st;
#pragma unroll
    for (int off = 16; off; off >>= 1) sc += __shfl_xor_sync(FULLM, sc, off);

    if (lane == 0) {
        const float LN2 = 0.6931471805599453f;
        float logZ = (g_cfw[seq] + g_cbw[seq]) * LN2 + __logf(pv);
        g_res[seq] = sc - logZ;
    }
}

// ---------------------------------------------------------------------------
// Kernel 4: mean -> d_out[0]
// ---------------------------------------------------------------------------
__global__ __launch_bounds__(256) void reduce_kernel(float* __restrict__ out) {
    const int tid = threadIdx.x;
    float val = g_res[tid];
#pragma unroll
    for (int off = 16; off; off >>= 1) val += __shfl_xor_sync(FULLM, val, off);

    __shared__ float sh[8];
    if ((tid & 31) == 0) sh[tid >> 5] = val;
    __syncthreads();
    if (tid < 8) {
        float t = sh[tid];
#pragma unroll
        for (int off = 4; off; off >>= 1) t += __shfl_xor_sync(0xffu, t, off);
        if (tid == 0) out[0] = t * (1.0f / 256.0f);
    }
}

// ---------------------------------------------------------------------------
extern "C" void kernel_launch(void* const* d_in, const int* in_sizes, int n_in,
                              void* d_out, int out_size) {
    const float* X      = (const float*)d_in[0];   // [256,1024,128] f32
    const int*   labels = (const int*)d_in[1];     // [256,1024] i32
    const float* W      = (const float*)d_in[2];   // [26,128] f32
    const float* Tm     = (const float*)d_in[3];   // [26,26] f32

    emis_hmma<<<2048, 128>>>(X, W);
    scan_kernel<<<2 * B_, 32>>>(Tm);
    score_combine<<<B_, 32>>>(labels, Tm);
    reduce_kernel<<<1, 256>>>((float*)d_out);
}